// round 1
// baseline (speedup 1.0000x reference)
#include <cuda_runtime.h>
#include <math.h>

#define W 1024
#define H 1024
#define B 4
#define NPTS 262144
#define HW (W * H)

// Scratch: per-pixel erosion weight map ("mask_erode" in the reference)
__device__ float g_erode[B * HW];

// ---------------------------------------------------------------------------
// Kernel 1: collapse the 15x (7x7 min-pool) erosion-weight loop into a single
// Chebyshev-distance computation.
//   d = Chebyshev distance to nearest in-image zero pixel
//   weight(p) = 0                      if mask(p)==0
//             = 1                      if d > 45
//             = 0.1 + 0.06*(ceil(d/3)-1)  otherwise
// ---------------------------------------------------------------------------
#define TX 32
#define TY 16
#define HALO 3
#define SW (TX + 2 * HALO)   // 38
#define SH (TY + 2 * HALO)   // 22

__global__ void erode_weight_kernel(const float* __restrict__ mask,
                                    float* __restrict__ out) {
    __shared__ float sm[SH][SW + 2];  // +2 pad to dodge bank conflicts

    const int b = blockIdx.z;
    const float* m = mask + (size_t)b * HW;

    const int gx0 = blockIdx.x * TX - HALO;
    const int gy0 = blockIdx.y * TY - HALO;
    const int tid = threadIdx.y * TX + threadIdx.x;

    // Cooperative tile + halo load; OOB behaves as "1" (never a zero source)
    for (int i = tid; i < SH * SW; i += TX * TY) {
        int r = i / SW, c = i % SW;
        int gy = gy0 + r, gx = gx0 + c;
        float v = 1.0f;
        if (gx >= 0 && gx < W && gy >= 0 && gy < H)
            v = __ldg(&m[gy * W + gx]);
        sm[r][c] = v;
    }
    __syncthreads();

    const int lx = threadIdx.x + HALO;
    const int ly = threadIdx.y + HALO;
    const int x = blockIdx.x * TX + threadIdx.x;
    const int y = blockIdx.y * TY + threadIdx.y;

    const float c = sm[ly][lx];
    float wgt;
    if (c == 0.0f) {
        wgt = 0.0f;
    } else {
        int d = 46;  // 46 == "no zero within radius 45"
        // Rings 1..3 from shared memory (covers ~all pixels for random masks)
        #pragma unroll
        for (int r = 1; r <= HALO; r++) {
            if (d != 46) break;
            float mn = 1.0f;
            #pragma unroll
            for (int dx = -3; dx <= 3; dx++) {
                if (dx < -r || dx > r) continue;
                mn = fminf(mn, sm[ly - r][lx + dx]);
                mn = fminf(mn, sm[ly + r][lx + dx]);
            }
            #pragma unroll
            for (int dy = -2; dy <= 2; dy++) {
                if (dy <= -r || dy >= r) continue;
                mn = fminf(mn, sm[ly + dy][lx - r]);
                mn = fminf(mn, sm[ly + dy][lx + r]);
            }
            if (mn == 0.0f) d = r;
        }
        // Exact fallback: rings 4..45 from global memory (astronomically rare)
        if (d == 46) {
            for (int r = HALO + 1; r <= 45 && d == 46; r++) {
                float mn = 1.0f;
                int xa = max(x - r, 0), xb = min(x + r, W - 1);
                if (y - r >= 0)
                    for (int xx = xa; xx <= xb; xx++)
                        mn = fminf(mn, __ldg(&m[(y - r) * W + xx]));
                if (y + r < H)
                    for (int xx = xa; xx <= xb; xx++)
                        mn = fminf(mn, __ldg(&m[(y + r) * W + xx]));
                int ya = max(y - r + 1, 0), yb = min(y + r - 1, H - 1);
                if (x - r >= 0)
                    for (int yy = ya; yy <= yb; yy++)
                        mn = fminf(mn, __ldg(&m[yy * W + (x - r)]));
                if (x + r < W)
                    for (int yy = ya; yy <= yb; yy++)
                        mn = fminf(mn, __ldg(&m[yy * W + (x + r)]));
                if (mn == 0.0f) d = r;
            }
        }
        if (d >= 46) {
            wgt = 1.0f;  // survives all 15 erosions
        } else {
            int i = (d + 2) / 3 - 1;  // ceil(d/3) - 1, in 0..14
            wgt = 0.1f + (float)i * (0.9f / 15.0f);
        }
    }
    out[(size_t)b * HW + y * W + x] = wgt;
}

// ---------------------------------------------------------------------------
// Kernel 2: per-point bilinear sampling + fusion
// ---------------------------------------------------------------------------
__device__ __forceinline__ float bilerp(const float* __restrict__ img,
                                        int i00, int i01, int i10, int i11,
                                        float w00, float w01, float w10, float w11) {
    return __ldg(&img[i00]) * w00 + __ldg(&img[i01]) * w01 +
           __ldg(&img[i10]) * w10 + __ldg(&img[i11]) * w11;
}

__global__ void fuse_kernel(const float* __restrict__ face_depth,
                            const float* __restrict__ edge_mask,
                            const float* __restrict__ xy,
                            const float* __restrict__ z,
                            const float* __restrict__ occ_body,
                            const float* __restrict__ occ_face,
                            const float* __restrict__ erode,
                            float* __restrict__ out) {
    int idx = blockIdx.x * blockDim.x + threadIdx.x;
    if (idx >= B * NPTS) return;
    int b = idx / NPTS;
    int n = idx - b * NPTS;

    float px = __ldg(&xy[(size_t)b * 2 * NPTS + n]);
    float py = __ldg(&xy[(size_t)b * 2 * NPTS + NPTS + n]);
    float xf = (px + 1.0f) * 0.5f * (float)(W - 1);
    float yf = (py + 1.0f) * 0.5f * (float)(H - 1);
    float x0f = floorf(xf), y0f = floorf(yf);
    float wx = xf - x0f, wy = yf - y0f;
    int x0 = min(max((int)x0f, 0), W - 1);
    int x1 = min(max((int)x0f + 1, 0), W - 1);
    int y0 = min(max((int)y0f, 0), H - 1);
    int y1 = min(max((int)y0f + 1, 0), H - 1);

    size_t base = (size_t)b * HW;
    int i00 = (int)(y0 * W + x0), i01 = (int)(y0 * W + x1);
    int i10 = (int)(y1 * W + x0), i11 = (int)(y1 * W + x1);
    float w00 = (1.0f - wx) * (1.0f - wy);
    float w01 = wx * (1.0f - wy);
    float w10 = (1.0f - wx) * wy;
    float w11 = wx * wy;

    const float* em = edge_mask + base;
    float edge = bilerp(em, i00, i01, i10, i11, w00, w01, w10, w11);

    float ob = __ldg(&occ_body[idx]);
    float res;
    if (edge > 0.01f) {
        const float* fd = face_depth + base;
        const float* er = erode + base;
        float depth_q = bilerp(fd, i00, i01, i10, i11, w00, w01, w10, w11);
        float labels  = bilerp(er, i00, i01, i10, i11, w00, w01, w10, w11);
        float psdf = __ldg(&z[idx]) - depth_q;
        float w = expf(-psdf * psdf * 1000.0f) * labels;
        res = w * __ldg(&occ_face[idx]) + (1.0f - w) * ob;
    } else {
        // edge_b == 0  =>  labels == 0  =>  w == 0
        res = ob;
    }
    out[idx] = res;
}

// ---------------------------------------------------------------------------
// Launch
// inputs: 0 mask, 1 face_depth, 2 face_depth_edge_mask, 3 xy, 4 z,
//         5 occ_body, 6 occ_face ; output: [B,1,NPTS] float
// ---------------------------------------------------------------------------
extern "C" void kernel_launch(void* const* d_in, const int* in_sizes, int n_in,
                              void* d_out, int out_size) {
    const float* mask      = (const float*)d_in[0];
    const float* face_depth = (const float*)d_in[1];
    const float* edge_mask = (const float*)d_in[2];
    const float* xy        = (const float*)d_in[3];
    const float* z         = (const float*)d_in[4];
    const float* occ_body  = (const float*)d_in[5];
    const float* occ_face  = (const float*)d_in[6];
    float* out = (float*)d_out;

    float* erode_ptr;
    cudaGetSymbolAddress((void**)&erode_ptr, g_erode);

    dim3 eb(TX, TY);
    dim3 eg(W / TX, H / TY, B);
    erode_weight_kernel<<<eg, eb>>>(mask, erode_ptr);

    int threads = 256;
    int blocks = (B * NPTS + threads - 1) / threads;
    fuse_kernel<<<blocks, threads>>>(face_depth, edge_mask, xy, z,
                                     occ_body, occ_face, erode_ptr, out);
}

// round 2
// speedup vs baseline: 1.0465x; 1.0465x over previous
#include <cuda_runtime.h>
#include <math.h>

#define W 1024
#define H 1024
#define B 4
#define NPTS 262144
#define HW (W * H)

// Packed per-pixel map: .x = depth bits (fp32), .y = (edge?0xFFFF0000:0) | erode_q16
__device__ uint2 g_map[B * HW];

// ---------------------------------------------------------------------------
// Exact (rare) fallback: Chebyshev ring scan for d in [4,45]; else weight 1.0
// ---------------------------------------------------------------------------
__device__ __noinline__ float erode_fallback(const float* __restrict__ m,
                                             int x, int y) {
    for (int r = 4; r <= 45; r++) {
        float mn = 1.0f;
        int xa = max(x - r, 0), xb = min(x + r, W - 1);
        if (y - r >= 0)
            for (int xx = xa; xx <= xb; xx++)
                mn = fminf(mn, __ldg(&m[(y - r) * W + xx]));
        if (y + r < H)
            for (int xx = xa; xx <= xb; xx++)
                mn = fminf(mn, __ldg(&m[(y + r) * W + xx]));
        int ya = max(y - r + 1, 0), yb = min(y + r - 1, H - 1);
        if (x - r >= 0)
            for (int yy = ya; yy <= yb; yy++)
                mn = fminf(mn, __ldg(&m[yy * W + (x - r)]));
        if (x + r < W)
            for (int yy = ya; yy <= yb; yy++)
                mn = fminf(mn, __ldg(&m[yy * W + (x + r)]));
        if (mn == 0.0f) {
            int i = (r + 2) / 3 - 1;                  // ceil(r/3)-1
            double rate = 0.1 + (double)i * 0.06;     // match reference arithmetic
            return (float)(rate < 1.0 ? rate : 1.0);
        }
    }
    return 1.0f;
}

// ---------------------------------------------------------------------------
// Kernel 1: bitmap erosion (ballot + funnel shifts) fused with map packing.
// Tile: 8 words (256 px) wide x 32 rows. Halo: 1 word horiz, 3 rows vert.
// ---------------------------------------------------------------------------
#define WORDS 8
#define TY 32
#define LROWS (TY + 6)       // 38
#define LWORDS (WORDS + 2)   // 10

__global__ void pack_kernel(const float* __restrict__ mask,
                            const float* __restrict__ depth,
                            const float* __restrict__ edge,
                            uint2* __restrict__ out) {
    __shared__ unsigned zb[LROWS][LWORDS];   // zero-bitmaps (bit=1 -> mask==0)
    __shared__ unsigned hd[LROWS][WORDS];    // horizontally dilated (+/-3)

    const int b = blockIdx.z;
    const float* m = mask + (size_t)b * HW;
    const float* dp = depth + (size_t)b * HW;
    const float* eg = edge + (size_t)b * HW;
    uint2* op = out + (size_t)b * HW;

    const int x0 = blockIdx.x * (WORDS * 32);
    const int y0 = blockIdx.y * TY;
    const int warp = threadIdx.x >> 5;
    const int lane = threadIdx.x & 31;

    // Phase 1: load zero-bitmaps via ballot (whole word uniformly in/out of image)
    for (int i = warp; i < LROWS * LWORDS; i += 8) {
        int r = i / LWORDS, c = i % LWORDS;
        int gy = y0 - 3 + r;
        int gxw = x0 + (c - 1) * 32;       // word base x
        bool zero = false;
        if (gy >= 0 && gy < H && gxw >= 0 && gxw < W)
            zero = (__ldg(&m[gy * W + gxw + lane]) == 0.0f);
        unsigned wrd = __ballot_sync(0xffffffffu, zero);
        if (lane == 0) zb[r][c] = wrd;
    }
    __syncthreads();

    // Phase 2: horizontal dilation by 3 using funnel shifts
    for (int i = threadIdx.x; i < LROWS * WORDS; i += 256) {
        int r = i / WORDS, c = i % WORDS;
        unsigned wm = zb[r][c + 1], L = zb[r][c], R = zb[r][c + 2];
        unsigned h = wm;
        h |= __funnelshift_r(wm, R, 1) | __funnelshift_l(L, wm, 1);
        h |= __funnelshift_r(wm, R, 2) | __funnelshift_l(L, wm, 2);
        h |= __funnelshift_r(wm, R, 3) | __funnelshift_l(L, wm, 3);
        hd[r][c] = h;
    }
    __syncthreads();

    // Phase 3: vertical OR (7 rows) + finalize + pack
    for (int k = warp; k < TY * WORDS; k += 8) {
        int r = k / WORDS, c = k % WORDS;   // output row/word within tile
        unsigned v = hd[r][c] | hd[r + 1][c] | hd[r + 2][c] | hd[r + 3][c]
                   | hd[r + 4][c] | hd[r + 5][c] | hd[r + 6][c];
        unsigned cz = zb[r + 3][c + 1];

        int gy = y0 + r;
        int gx = x0 + c * 32 + lane;
        int gi = gy * W + gx;

        float w;
        if ((cz >> lane) & 1u)       w = 0.0f;   // center is zero
        else if ((v >> lane) & 1u)   w = 0.1f;   // zero within Chebyshev 3
        else                         w = erode_fallback(m, gx, gy);  // ~never

        float dv = __ldg(&dp[gi]);
        float ev = __ldg(&eg[gi]);
        unsigned code = (unsigned)lrintf(w * 65535.0f);
        unsigned hi = (ev != 0.0f) ? 0xFFFF0000u : 0u;
        op[gi] = make_uint2(__float_as_uint(dv), hi | code);
    }
}

// ---------------------------------------------------------------------------
// Kernel 2: per-point fusion — 4 packed gathers per point (was 12)
// ---------------------------------------------------------------------------
__global__ void fuse_kernel(const uint2* __restrict__ map,
                            const float* __restrict__ xy,
                            const float* __restrict__ z,
                            const float* __restrict__ occ_body,
                            const float* __restrict__ occ_face,
                            float* __restrict__ out) {
    int idx = blockIdx.x * blockDim.x + threadIdx.x;
    if (idx >= B * NPTS) return;
    int b = idx >> 18;            // NPTS = 2^18
    int n = idx & (NPTS - 1);

    float px = __ldg(&xy[(size_t)b * 2 * NPTS + n]);
    float py = __ldg(&xy[(size_t)b * 2 * NPTS + NPTS + n]);
    float xf = (px + 1.0f) * 0.5f * (float)(W - 1);
    float yf = (py + 1.0f) * 0.5f * (float)(H - 1);
    float x0f = floorf(xf), y0f = floorf(yf);
    float wx = xf - x0f, wy = yf - y0f;
    int x0 = min(max((int)x0f, 0), W - 1);
    int x1 = min(max((int)x0f + 1, 0), W - 1);
    int y0 = min(max((int)y0f, 0), H - 1);
    int y1 = min(max((int)y0f + 1, 0), H - 1);

    const uint2* mp = map + (size_t)b * HW;
    uint2 p00 = __ldg(&mp[y0 * W + x0]);
    uint2 p01 = __ldg(&mp[y0 * W + x1]);
    uint2 p10 = __ldg(&mp[y1 * W + x0]);
    uint2 p11 = __ldg(&mp[y1 * W + x1]);

    float w00 = (1.0f - wx) * (1.0f - wy);
    float w01 = wx * (1.0f - wy);
    float w10 = (1.0f - wx) * wy;
    float w11 = wx * wy;

    // edge bilinear (corners are exactly 0/1)
    float e00 = (p00.y & 0xFFFF0000u) ? 1.0f : 0.0f;
    float e01 = (p01.y & 0xFFFF0000u) ? 1.0f : 0.0f;
    float e10 = (p10.y & 0xFFFF0000u) ? 1.0f : 0.0f;
    float e11 = (p11.y & 0xFFFF0000u) ? 1.0f : 0.0f;
    float edge = e00 * w00 + e01 * w01 + e10 * w10 + e11 * w11;

    float ob = __ldg(&occ_body[idx]);
    float res = ob;
    if (edge > 0.01f) {
        float dq = __uint_as_float(p00.x) * w00 + __uint_as_float(p01.x) * w01
                 + __uint_as_float(p10.x) * w10 + __uint_as_float(p11.x) * w11;
        const float s = 1.0f / 65535.0f;
        float labels = (float)(p00.y & 0xFFFFu) * s * w00
                     + (float)(p01.y & 0xFFFFu) * s * w01
                     + (float)(p10.y & 0xFFFFu) * s * w10
                     + (float)(p11.y & 0xFFFFu) * s * w11;
        float psdf = __ldg(&z[idx]) - dq;
        float wgt = expf(-psdf * psdf * 1000.0f) * labels;
        res = wgt * __ldg(&occ_face[idx]) + (1.0f - wgt) * ob;
    }
    out[idx] = res;
}

// ---------------------------------------------------------------------------
// Launch.  inputs: 0 mask, 1 face_depth, 2 face_depth_edge_mask, 3 xy, 4 z,
//                  5 occ_body, 6 occ_face ; output: [B,1,NPTS] float
// ---------------------------------------------------------------------------
extern "C" void kernel_launch(void* const* d_in, const int* in_sizes, int n_in,
                              void* d_out, int out_size) {
    const float* mask       = (const float*)d_in[0];
    const float* face_depth = (const float*)d_in[1];
    const float* edge_mask  = (const float*)d_in[2];
    const float* xy         = (const float*)d_in[3];
    const float* z          = (const float*)d_in[4];
    const float* occ_body   = (const float*)d_in[5];
    const float* occ_face   = (const float*)d_in[6];
    float* out = (float*)d_out;

    uint2* map_ptr;
    cudaGetSymbolAddress((void**)&map_ptr, g_map);

    dim3 pg(W / (WORDS * 32), H / TY, B);   // (4, 32, 4)
    pack_kernel<<<pg, 256>>>(mask, face_depth, edge_mask, map_ptr);

    int threads = 256;
    int blocks = (B * NPTS + threads - 1) / threads;
    fuse_kernel<<<blocks, threads>>>(map_ptr, xy, z, occ_body, occ_face, out);
}

// round 3
// speedup vs baseline: 1.4850x; 1.4190x over previous
#include <cuda_runtime.h>
#include <math.h>

#define W 1024
#define H 1024
#define B 4
#define NPTS 262144
#define HW (W * H)

// Packed per-pixel map entry (8B): .x = depth fp32 bits,
// .y = (edge ? 0xFFFF0000 : 0) | erode_code_u16.  Stored as uint4 pairs for
// 16B-aligned paired gathers in fuse.
__device__ uint4 g_map4[B * HW / 2];

// ---------------------------------------------------------------------------
// Exact (rare) fallback: Chebyshev ring scan for d in [4,45]; else weight 1.0
// ---------------------------------------------------------------------------
__device__ __noinline__ unsigned erode_fallback_code(const float* __restrict__ m,
                                                     int x, int y) {
    for (int r = 4; r <= 45; r++) {
        float mn = 1.0f;
        int xa = max(x - r, 0), xb = min(x + r, W - 1);
        if (y - r >= 0)
            for (int xx = xa; xx <= xb; xx++)
                mn = fminf(mn, __ldg(&m[(y - r) * W + xx]));
        if (y + r < H)
            for (int xx = xa; xx <= xb; xx++)
                mn = fminf(mn, __ldg(&m[(y + r) * W + xx]));
        int ya = max(y - r + 1, 0), yb = min(y + r - 1, H - 1);
        if (x - r >= 0)
            for (int yy = ya; yy <= yb; yy++)
                mn = fminf(mn, __ldg(&m[yy * W + (x - r)]));
        if (x + r < W)
            for (int yy = ya; yy <= yb; yy++)
                mn = fminf(mn, __ldg(&m[yy * W + (x + r)]));
        if (mn == 0.0f) {
            int i = (r + 2) / 3 - 1;              // ceil(r/3)-1
            double rate = 0.1 + (double)i * 0.06;
            float w = (float)(rate < 1.0 ? rate : 1.0);
            return (unsigned)lrintf(w * 65535.0f);
        }
    }
    return 65535u;   // weight 1.0
}

// ---------------------------------------------------------------------------
// Kernel 1: bitmap erosion + map packing.  Full-width tiles: 1024 x TROWS.
// All phases are flat loops with independent iterations (high MLP).
// ---------------------------------------------------------------------------
#define TROWS 16
#define HR (TROWS + 6)       // 22 rows incl. vertical halo

__global__ void pack_kernel(const float* __restrict__ mask,
                            const float* __restrict__ depth,
                            const float* __restrict__ edge,
                            uint4* __restrict__ out4) {
    __shared__ unsigned zb[HR][32];     // zero bitmap (bit=1 -> mask==0)
    __shared__ unsigned hd[HR][32];     // horizontally dilated +/-3
    __shared__ unsigned vd[TROWS][32];  // 7x7 window OR

    const int b = blockIdx.y;
    const int y0 = blockIdx.x * TROWS;
    const int tid = threadIdx.x;
    const float* m  = mask  + (size_t)b * HW;
    const float* dp = depth + (size_t)b * HW;
    const float* eg = edge  + (size_t)b * HW;
    uint4* op = out4 + (size_t)b * (HW / 2);

    // Phase 1: each thread builds one 32-px zero-bit word from 8 float4 loads
    for (int g = tid; g < HR * 32; g += 256) {
        int r = g >> 5, c = g & 31;
        int gy = y0 - 3 + r;
        unsigned wrd = 0;
        if (gy >= 0 && gy < H) {
            const float4* p = (const float4*)&m[gy * W + c * 32];
            #pragma unroll
            for (int j = 0; j < 8; j++) {
                float4 v = __ldg(&p[j]);
                unsigned nb = (v.x == 0.0f ? 1u : 0u) | (v.y == 0.0f ? 2u : 0u)
                            | (v.z == 0.0f ? 4u : 0u) | (v.w == 0.0f ? 8u : 0u);
                wrd |= nb << (j * 4);
            }
        }
        zb[r][c] = wrd;
    }
    __syncthreads();

    // Phase 2: horizontal dilation by 3 (funnel shifts; image edge -> no zeros)
    for (int g = tid; g < HR * 32; g += 256) {
        int r = g >> 5, c = g & 31;
        unsigned wm = zb[r][c];
        unsigned L = c ? zb[r][c - 1] : 0u;
        unsigned R = (c < 31) ? zb[r][c + 1] : 0u;
        unsigned h = wm;
        h |= __funnelshift_r(wm, R, 1) | __funnelshift_l(L, wm, 1);
        h |= __funnelshift_r(wm, R, 2) | __funnelshift_l(L, wm, 2);
        h |= __funnelshift_r(wm, R, 3) | __funnelshift_l(L, wm, 3);
        hd[r][c] = h;
    }
    __syncthreads();

    // Phase 3: vertical OR over 7 rows
    for (int g = tid; g < TROWS * 32; g += 256) {
        int r = g >> 5, c = g & 31;
        vd[r][c] = hd[r][c] | hd[r + 1][c] | hd[r + 2][c] | hd[r + 3][c]
                 | hd[r + 4][c] | hd[r + 5][c] | hd[r + 6][c];
    }
    __syncthreads();

    // Phase 4: pack 4 px per iteration (float4 in, 2x uint4 out)
    #pragma unroll 4
    for (int g = tid; g < TROWS * 256; g += 256) {
        int r = g >> 8, q = g & 255;
        int x = q * 4;
        int gy = y0 + r;
        unsigned zn = (zb[r + 3][x >> 5] >> (x & 31)) & 0xFu;
        unsigned vn = (vd[r][x >> 5] >> (x & 31)) & 0xFu;
        size_t gi = (size_t)gy * W + x;
        float4 d4 = __ldg((const float4*)&dp[gi]);
        float4 e4 = __ldg((const float4*)&eg[gi]);

        unsigned code[4];
        #pragma unroll
        for (int i = 0; i < 4; i++) {
            unsigned c2;
            if (zn & (1u << i))      c2 = 0u;
            else if (vn & (1u << i)) c2 = 6554u;  // round(0.1*65535)
            else                     c2 = erode_fallback_code(m, x + i, gy);
            code[i] = c2;
        }
        const float* ep = &e4.x;
        const float* dpx = &d4.x;
        uint4 o0, o1;
        o0.x = __float_as_uint(dpx[0]);
        o0.y = code[0] | (ep[0] != 0.0f ? 0xFFFF0000u : 0u);
        o0.z = __float_as_uint(dpx[1]);
        o0.w = code[1] | (ep[1] != 0.0f ? 0xFFFF0000u : 0u);
        o1.x = __float_as_uint(dpx[2]);
        o1.y = code[2] | (ep[2] != 0.0f ? 0xFFFF0000u : 0u);
        o1.z = __float_as_uint(dpx[3]);
        o1.w = code[3] | (ep[3] != 0.0f ? 0xFFFF0000u : 0u);
        op[gi >> 1]       = o0;
        op[(gi >> 1) + 1] = o1;
    }
}

// ---------------------------------------------------------------------------
// Kernel 2: fusion, 4 points/thread, paired 16B-aligned gathers
// ---------------------------------------------------------------------------
__device__ __forceinline__ uint2 sel_half(uint4 v, int odd) {
    return odd ? make_uint2(v.z, v.w) : make_uint2(v.x, v.y);
}

__global__ void fuse_kernel(const uint4* __restrict__ map4,
                            const float* __restrict__ xy,
                            const float* __restrict__ z,
                            const float* __restrict__ occ_body,
                            const float* __restrict__ occ_face,
                            float* __restrict__ out) {
    int t = blockIdx.x * blockDim.x + threadIdx.x;   // 0 .. B*NPTS/4-1
    int idx0 = t * 4;
    int b = idx0 >> 18;                               // NPTS = 2^18
    int n0 = idx0 & (NPTS - 1);

    const float4 x4 = __ldg((const float4*)&xy[(size_t)b * 2 * NPTS + n0]);
    const float4 y4 = __ldg((const float4*)&xy[(size_t)b * 2 * NPTS + NPTS + n0]);
    const float4 z4 = __ldg((const float4*)&z[idx0]);
    const float4 ob4 = __ldg((const float4*)&occ_body[idx0]);
    const float4 of4 = __ldg((const float4*)&occ_face[idx0]);
    const uint4* mp = map4 + (size_t)b * (HW / 2);

    float px[4] = {x4.x, x4.y, x4.z, x4.w};
    float py[4] = {y4.x, y4.y, y4.z, y4.w};
    float zz[4] = {z4.x, z4.y, z4.z, z4.w};
    float ob[4] = {ob4.x, ob4.y, ob4.z, ob4.w};
    float of[4] = {of4.x, of4.y, of4.z, of4.w};
    float res[4];

    #pragma unroll
    for (int i = 0; i < 4; i++) {
        float xf = (px[i] + 1.0f) * 0.5f * (float)(W - 1);
        float yf = (py[i] + 1.0f) * 0.5f * (float)(H - 1);
        float x0f = floorf(xf), y0f = floorf(yf);
        float wx = xf - x0f, wy = yf - y0f;
        int x0 = min(max((int)x0f, 0), W - 1);
        int x1 = min(max((int)x0f + 1, 0), W - 1);
        int y0 = min(max((int)y0f, 0), H - 1);
        int y1 = min(max((int)y0f + 1, 0), H - 1);

        int i00 = y0 * W + x0, i01 = y0 * W + x1;
        int i10 = y1 * W + x0, i11 = y1 * W + x1;

        // top row: one aligned 16B load, second predicated (~50% of lanes)
        uint4 A = __ldg(&mp[i00 >> 1]);
        uint4 Bv = A;
        if ((i01 >> 1) != (i00 >> 1)) Bv = __ldg(&mp[i01 >> 1]);
        uint2 p00 = sel_half(A, i00 & 1);
        uint2 p01 = sel_half(Bv, i01 & 1);
        // bottom row
        uint4 C = __ldg(&mp[i10 >> 1]);
        uint4 Dv = C;
        if ((i11 >> 1) != (i10 >> 1)) Dv = __ldg(&mp[i11 >> 1]);
        uint2 p10 = sel_half(C, i10 & 1);
        uint2 p11 = sel_half(Dv, i11 & 1);

        float w00 = (1.0f - wx) * (1.0f - wy);
        float w01 = wx * (1.0f - wy);
        float w10 = (1.0f - wx) * wy;
        float w11 = wx * wy;

        float e00 = (p00.y >> 16) ? 1.0f : 0.0f;
        float e01 = (p01.y >> 16) ? 1.0f : 0.0f;
        float e10 = (p10.y >> 16) ? 1.0f : 0.0f;
        float e11 = (p11.y >> 16) ? 1.0f : 0.0f;
        float edgev = e00 * w00 + e01 * w01 + e10 * w10 + e11 * w11;

        float dq = __uint_as_float(p00.x) * w00 + __uint_as_float(p01.x) * w01
                 + __uint_as_float(p10.x) * w10 + __uint_as_float(p11.x) * w11;
        const float s = 1.0f / 65535.0f;
        float labels = (float)(p00.y & 0xFFFFu) * (w00 * s)
                     + (float)(p01.y & 0xFFFFu) * (w01 * s)
                     + (float)(p10.y & 0xFFFFu) * (w10 * s)
                     + (float)(p11.y & 0xFFFFu) * (w11 * s);
        float psdf = zz[i] - dq;
        float wgt = __expf(-psdf * psdf * 1000.0f) * labels;
        float r2 = wgt * of[i] + (1.0f - wgt) * ob[i];
        res[i] = (edgev > 0.01f) ? r2 : ob[i];
    }

    *(float4*)&out[idx0] = make_float4(res[0], res[1], res[2], res[3]);
}

// ---------------------------------------------------------------------------
// Launch.  inputs: 0 mask, 1 face_depth, 2 face_depth_edge_mask, 3 xy, 4 z,
//                  5 occ_body, 6 occ_face ; output: [B,1,NPTS] float
// ---------------------------------------------------------------------------
extern "C" void kernel_launch(void* const* d_in, const int* in_sizes, int n_in,
                              void* d_out, int out_size) {
    const float* mask       = (const float*)d_in[0];
    const float* face_depth = (const float*)d_in[1];
    const float* edge_mask  = (const float*)d_in[2];
    const float* xy         = (const float*)d_in[3];
    const float* z          = (const float*)d_in[4];
    const float* occ_body   = (const float*)d_in[5];
    const float* occ_face   = (const float*)d_in[6];
    float* out = (float*)d_out;

    uint4* map_ptr;
    cudaGetSymbolAddress((void**)&map_ptr, g_map4);

    dim3 pg(H / TROWS, B);   // (64, 4) = 256 blocks
    pack_kernel<<<pg, 256>>>(mask, face_depth, edge_mask, map_ptr);

    int blocks = (B * NPTS / 4) / 256;   // 1024
    fuse_kernel<<<blocks, 256>>>(map_ptr, xy, z, occ_body, occ_face, out);
}

// round 4
// speedup vs baseline: 1.5719x; 1.0585x over previous
#include <cuda_runtime.h>
#include <math.h>

#define W 1024
#define H 1024
#define B 4
#define NPTS 262144
#define HW (W * H)

// Packed per-pixel map entry (8B): .x = depth fp32 bits,
// .y = (edge ? 0xFFFF0000 : 0) | erode_code_u16
// Declared as uint4 for 16B-aligned vectorized stores in pack; fuse reads uint2.
__device__ uint4 g_map4[B * HW / 2];

// ---------------------------------------------------------------------------
// Exact (rare) fallback: Chebyshev ring scan for d in [4,45]; else weight 1.0
// ---------------------------------------------------------------------------
__device__ __noinline__ unsigned erode_fallback_code(const float* __restrict__ m,
                                                     int x, int y) {
    for (int r = 4; r <= 45; r++) {
        float mn = 1.0f;
        int xa = max(x - r, 0), xb = min(x + r, W - 1);
        if (y - r >= 0)
            for (int xx = xa; xx <= xb; xx++)
                mn = fminf(mn, __ldg(&m[(y - r) * W + xx]));
        if (y + r < H)
            for (int xx = xa; xx <= xb; xx++)
                mn = fminf(mn, __ldg(&m[(y + r) * W + xx]));
        int ya = max(y - r + 1, 0), yb = min(y + r - 1, H - 1);
        if (x - r >= 0)
            for (int yy = ya; yy <= yb; yy++)
                mn = fminf(mn, __ldg(&m[yy * W + (x - r)]));
        if (x + r < W)
            for (int yy = ya; yy <= yb; yy++)
                mn = fminf(mn, __ldg(&m[yy * W + (x + r)]));
        if (mn == 0.0f) {
            int i = (r + 2) / 3 - 1;              // ceil(r/3)-1
            double rate = 0.1 + (double)i * 0.06;
            float w = (float)(rate < 1.0 ? rate : 1.0);
            return (unsigned)lrintf(w * 65535.0f);
        }
    }
    return 65535u;   // weight 1.0
}

// ---------------------------------------------------------------------------
// Kernel 1: bitmap erosion + map packing.  Full-width tiles: 1024 x TROWS.
// ---------------------------------------------------------------------------
#define TROWS 8
#define HR (TROWS + 6)       // 14 rows incl. vertical halo

__global__ void pack_kernel(const float* __restrict__ mask,
                            const float* __restrict__ depth,
                            const float* __restrict__ edge,
                            uint4* __restrict__ out4) {
    __shared__ unsigned zb[HR][32];     // zero bitmap (bit=1 -> mask==0)
    __shared__ unsigned hd[HR][32];     // horizontally dilated +/-3
    __shared__ unsigned vd[TROWS][32];  // 7x7 window OR

    const int b = blockIdx.y;
    const int y0 = blockIdx.x * TROWS;
    const int tid = threadIdx.x;
    const float* m  = mask  + (size_t)b * HW;
    const float* dp = depth + (size_t)b * HW;
    const float* eg = edge  + (size_t)b * HW;
    uint4* op = out4 + (size_t)b * (HW / 2);

    // Phase 1: each thread builds one 32-px zero-bit word from 8 float4 loads
    for (int g = tid; g < HR * 32; g += 256) {
        int r = g >> 5, c = g & 31;
        int gy = y0 - 3 + r;
        unsigned wrd = 0;
        if (gy >= 0 && gy < H) {
            const float4* p = (const float4*)&m[gy * W + c * 32];
            #pragma unroll
            for (int j = 0; j < 8; j++) {
                float4 v = __ldg(&p[j]);
                unsigned nb = (v.x == 0.0f ? 1u : 0u) | (v.y == 0.0f ? 2u : 0u)
                            | (v.z == 0.0f ? 4u : 0u) | (v.w == 0.0f ? 8u : 0u);
                wrd |= nb << (j * 4);
            }
        }
        zb[r][c] = wrd;
    }
    __syncthreads();

    // Phase 2: horizontal dilation by 3 (funnel shifts; outside image = no zeros)
    for (int g = tid; g < HR * 32; g += 256) {
        int r = g >> 5, c = g & 31;
        unsigned wm = zb[r][c];
        unsigned L = c ? zb[r][c - 1] : 0u;
        unsigned R = (c < 31) ? zb[r][c + 1] : 0u;
        unsigned h = wm;
        h |= __funnelshift_r(wm, R, 1) | __funnelshift_l(L, wm, 1);
        h |= __funnelshift_r(wm, R, 2) | __funnelshift_l(L, wm, 2);
        h |= __funnelshift_r(wm, R, 3) | __funnelshift_l(L, wm, 3);
        hd[r][c] = h;
    }
    __syncthreads();

    // Phase 3: vertical OR over 7 rows
    for (int g = tid; g < TROWS * 32; g += 256) {
        int r = g >> 5, c = g & 31;
        vd[r][c] = hd[r][c] | hd[r + 1][c] | hd[r + 2][c] | hd[r + 3][c]
                 | hd[r + 4][c] | hd[r + 5][c] | hd[r + 6][c];
    }
    __syncthreads();

    // Phase 4: pack 4 px per iteration (float4 in, 2x uint4 out)
    #pragma unroll 4
    for (int g = tid; g < TROWS * 256; g += 256) {
        int r = g >> 8, q = g & 255;
        int x = q * 4;
        int gy = y0 + r;
        unsigned zn = (zb[r + 3][x >> 5] >> (x & 31)) & 0xFu;
        unsigned vn = (vd[r][x >> 5] >> (x & 31)) & 0xFu;
        size_t gi = (size_t)gy * W + x;
        float4 d4 = __ldg((const float4*)&dp[gi]);
        float4 e4 = __ldg((const float4*)&eg[gi]);

        unsigned code[4];
        #pragma unroll
        for (int i = 0; i < 4; i++) {
            unsigned c2;
            if (zn & (1u << i))      c2 = 0u;
            else if (vn & (1u << i)) c2 = 6554u;  // round(0.1*65535)
            else                     c2 = erode_fallback_code(m, x + i, gy);
            code[i] = c2;
        }
        const float* ep = &e4.x;
        const float* dpx = &d4.x;
        uint4 o0, o1;
        o0.x = __float_as_uint(dpx[0]);
        o0.y = code[0] | (ep[0] != 0.0f ? 0xFFFF0000u : 0u);
        o0.z = __float_as_uint(dpx[1]);
        o0.w = code[1] | (ep[1] != 0.0f ? 0xFFFF0000u : 0u);
        o1.x = __float_as_uint(dpx[2]);
        o1.y = code[2] | (ep[2] != 0.0f ? 0xFFFF0000u : 0u);
        o1.z = __float_as_uint(dpx[3]);
        o1.w = code[3] | (ep[3] != 0.0f ? 0xFFFF0000u : 0u);
        op[gi >> 1]       = o0;
        op[(gi >> 1) + 1] = o1;
    }
}

// ---------------------------------------------------------------------------
// Kernel 2: fusion — 2 points/thread, 8 independent uint2 gathers in flight
// ---------------------------------------------------------------------------
__global__ void fuse_kernel(const uint2* __restrict__ map,
                            const float* __restrict__ xy,
                            const float* __restrict__ z,
                            const float* __restrict__ occ_body,
                            const float* __restrict__ occ_face,
                            float* __restrict__ out) {
    int t = blockIdx.x * blockDim.x + threadIdx.x;   // 0 .. B*NPTS/2-1
    int idx0 = t * 2;
    int b = idx0 >> 18;                               // NPTS = 2^18
    int n0 = idx0 & (NPTS - 1);

    const float2 x2  = __ldg((const float2*)&xy[(size_t)b * 2 * NPTS + n0]);
    const float2 y2  = __ldg((const float2*)&xy[(size_t)b * 2 * NPTS + NPTS + n0]);
    const float2 z2  = __ldg((const float2*)&z[idx0]);
    const float2 ob2 = __ldg((const float2*)&occ_body[idx0]);
    const float2 of2 = __ldg((const float2*)&occ_face[idx0]);
    const uint2* mp = map + (size_t)b * HW;

    float px[2] = {x2.x, x2.y};
    float py[2] = {y2.x, y2.y};
    float zz[2] = {z2.x, z2.y};
    float ob[2] = {ob2.x, ob2.y};
    float of[2] = {of2.x, of2.y};

    // Compute all 8 gather indices first, then issue all 8 loads (MLP=8)
    int i00[2], i01[2], i10[2], i11[2];
    float wx[2], wy[2];
    #pragma unroll
    for (int i = 0; i < 2; i++) {
        float xf = (px[i] + 1.0f) * 0.5f * (float)(W - 1);
        float yf = (py[i] + 1.0f) * 0.5f * (float)(H - 1);
        float x0f = floorf(xf), y0f = floorf(yf);
        wx[i] = xf - x0f;
        wy[i] = yf - y0f;
        int x0 = min(max((int)x0f, 0), W - 1);
        int x1 = min(max((int)x0f + 1, 0), W - 1);
        int y0 = min(max((int)y0f, 0), H - 1);
        int y1 = min(max((int)y0f + 1, 0), H - 1);
        i00[i] = y0 * W + x0; i01[i] = y0 * W + x1;
        i10[i] = y1 * W + x0; i11[i] = y1 * W + x1;
    }

    uint2 p00[2], p01[2], p10[2], p11[2];
    #pragma unroll
    for (int i = 0; i < 2; i++) {
        p00[i] = __ldg(&mp[i00[i]]);
        p01[i] = __ldg(&mp[i01[i]]);
        p10[i] = __ldg(&mp[i10[i]]);
        p11[i] = __ldg(&mp[i11[i]]);
    }

    float res[2];
    #pragma unroll
    for (int i = 0; i < 2; i++) {
        float w00 = (1.0f - wx[i]) * (1.0f - wy[i]);
        float w01 = wx[i] * (1.0f - wy[i]);
        float w10 = (1.0f - wx[i]) * wy[i];
        float w11 = wx[i] * wy[i];

        float e00 = (p00[i].y >> 16) ? 1.0f : 0.0f;
        float e01 = (p01[i].y >> 16) ? 1.0f : 0.0f;
        float e10 = (p10[i].y >> 16) ? 1.0f : 0.0f;
        float e11 = (p11[i].y >> 16) ? 1.0f : 0.0f;
        float edgev = e00 * w00 + e01 * w01 + e10 * w10 + e11 * w11;

        float dq = __uint_as_float(p00[i].x) * w00 + __uint_as_float(p01[i].x) * w01
                 + __uint_as_float(p10[i].x) * w10 + __uint_as_float(p11[i].x) * w11;
        const float s = 1.0f / 65535.0f;
        float labels = (float)(p00[i].y & 0xFFFFu) * (w00 * s)
                     + (float)(p01[i].y & 0xFFFFu) * (w01 * s)
                     + (float)(p10[i].y & 0xFFFFu) * (w10 * s)
                     + (float)(p11[i].y & 0xFFFFu) * (w11 * s);
        float psdf = zz[i] - dq;
        float wgt = __expf(-psdf * psdf * 1000.0f) * labels;
        float r2 = wgt * of[i] + (1.0f - wgt) * ob[i];
        res[i] = (edgev > 0.01f) ? r2 : ob[i];
    }

    *(float2*)&out[idx0] = make_float2(res[0], res[1]);
}

// ---------------------------------------------------------------------------
// Launch.  inputs: 0 mask, 1 face_depth, 2 face_depth_edge_mask, 3 xy, 4 z,
//                  5 occ_body, 6 occ_face ; output: [B,1,NPTS] float
// ---------------------------------------------------------------------------
extern "C" void kernel_launch(void* const* d_in, const int* in_sizes, int n_in,
                              void* d_out, int out_size) {
    const float* mask       = (const float*)d_in[0];
    const float* face_depth = (const float*)d_in[1];
    const float* edge_mask  = (const float*)d_in[2];
    const float* xy         = (const float*)d_in[3];
    const float* z          = (const float*)d_in[4];
    const float* occ_body   = (const float*)d_in[5];
    const float* occ_face   = (const float*)d_in[6];
    float* out = (float*)d_out;

    uint4* map_ptr;
    cudaGetSymbolAddress((void**)&map_ptr, g_map4);

    dim3 pg(H / TROWS, B);   // (128, 4) = 512 blocks
    pack_kernel<<<pg, 256>>>(mask, face_depth, edge_mask, map_ptr);

    int blocks = (B * NPTS / 2) / 256;   // 2048
    fuse_kernel<<<blocks, 256>>>((const uint2*)map_ptr, xy, z,
                                 occ_body, occ_face, out);
}